// round 17
// baseline (speedup 1.0000x reference)
#include <cuda_runtime.h>
#include <cuda_bf16.h>
#include <cstdint>

// Model constants
#define D_MODEL 128
#define VOCAB   4096
#define N_LAYERS 4
#define D_FF    512
#define D_INNER 256
#define D_STATE 16
#define D_CONV  4
#define DT_RANK 8
#define BB      8
#define LL      4096
#define NTOK    (BB*LL)   // 32768
#define NCHUNK  16
#define CLEN    256
#define SCH     64

// ---------------- scratch (device globals: no allocations allowed) ----------
__device__ float g_x [NTOK * D_MODEL];
__device__ float g_xz[NTOK * 2*D_INNER];
__device__ float g_u [NTOK * D_INNER];
__device__ float g_db[NTOK * 40];
__device__ __nv_bfloat16 g_uh[NTOK * D_INNER];
__device__ __nv_bfloat16 g_ul[NTOK * D_INNER];
__device__ __nv_bfloat16 g_ah[NTOK * D_FF];
__device__ __nv_bfloat16 g_al[NTOK * D_FF];
__device__ __nv_bfloat16 g_xh[NTOK * D_MODEL];
__device__ __nv_bfloat16 g_xl[NTOK * D_MODEL];
__device__ __nv_bfloat16 g_bh[VOCAB * D_FF];
__device__ __nv_bfloat16 g_bl[VOCAB * D_FF];
__device__ float g_S [BB * D_INNER * NCHUNK * D_STATE];
__device__ float g_Hc[BB * D_INNER * NCHUNK * D_STATE];
__device__ float g_Dc[BB * D_INNER * NCHUNK];

// ---------------- embedding gather ----------------
__global__ void embed_kernel(const int* __restrict__ tokens,
                             const float* __restrict__ emb,
                             float* __restrict__ x) {
    int idx = blockIdx.x * blockDim.x + threadIdx.x;
    int tok = idx >> 5;
    int j   = idx & 31;
    int t = tokens[tok];
    ((float4*)x)[idx] = ((const float4*)emb)[t * 32 + j];
}

// ---------------- LayerNorm fused with bf16 hi/lo split output --------------
__global__ void ln_split_kernel(const float* __restrict__ x,
                                const float* __restrict__ w,
                                const float* __restrict__ b,
                                __nv_bfloat16* __restrict__ oh,
                                __nv_bfloat16* __restrict__ ol) {
    int row  = blockIdx.x * blockDim.y + threadIdx.y;
    int lane = threadIdx.x;
    const float4* xr = (const float4*)(x + (size_t)row * D_MODEL);
    float4 v = xr[lane];
    float s = v.x + v.y + v.z + v.w;
    #pragma unroll
    for (int o = 16; o; o >>= 1) s += __shfl_xor_sync(0xffffffffu, s, o);
    float mu = s * (1.0f / 128.0f);
    float d0 = v.x - mu, d1 = v.y - mu, d2 = v.z - mu, d3 = v.w - mu;
    float vs = d0*d0 + d1*d1 + d2*d2 + d3*d3;
    #pragma unroll
    for (int o = 16; o; o >>= 1) vs += __shfl_xor_sync(0xffffffffu, vs, o);
    float inv = rsqrtf(vs * (1.0f / 128.0f) + 1e-5f);
    float4 wv = ((const float4*)w)[lane];
    float4 bv = ((const float4*)b)[lane];
    float o0 = d0 * inv * wv.x + bv.x;
    float o1 = d1 * inv * wv.y + bv.y;
    float o2 = d2 * inv * wv.z + bv.z;
    float o3 = d3 * inv * wv.w + bv.w;
    size_t base = (size_t)row * D_MODEL + lane * 4;
    __nv_bfloat162 h0 = __floats2bfloat162_rn(o0, o1);
    __nv_bfloat162 h1 = __floats2bfloat162_rn(o2, o3);
    __nv_bfloat162 l0 = __floats2bfloat162_rn(o0 - __bfloat162float(h0.x),
                                              o1 - __bfloat162float(h0.y));
    __nv_bfloat162 l1 = __floats2bfloat162_rn(o2 - __bfloat162float(h1.x),
                                              o3 - __bfloat162float(h1.y));
    *(__nv_bfloat162*)(oh + base)     = h0;
    *(__nv_bfloat162*)(oh + base + 2) = h1;
    *(__nv_bfloat162*)(ol + base)     = l0;
    *(__nv_bfloat162*)(ol + base + 2) = l1;
}

// ---------------- split + transpose B (zero-padded to grid width) -----------
__global__ void splitB_kernel(const float* __restrict__ B,
                              __nv_bfloat16* __restrict__ bth,
                              __nv_bfloat16* __restrict__ btl,
                              int K, int Nsrc) {
    __shared__ float t[32][33];
    int k0 = blockIdx.y * 32, n0 = blockIdx.x * 32;
    int tx = threadIdx.x, ty = threadIdx.y;  // (32, 8)
    #pragma unroll
    for (int yy = 0; yy < 4; yy++) {
        int n = n0 + tx;
        t[ty + 8 * yy][tx] = (n < Nsrc)
            ? B[(size_t)(k0 + ty + 8 * yy) * Nsrc + n] : 0.0f;
    }
    __syncthreads();
    #pragma unroll
    for (int yy = 0; yy < 4; yy++) {
        int n = n0 + ty + 8 * yy;
        float v = t[tx][ty + 8 * yy];
        __nv_bfloat16 h = __float2bfloat16(v);
        __nv_bfloat16 l = __float2bfloat16(v - __bfloat162float(h));
        bth[(size_t)n * K + k0 + tx] = h;
        btl[(size_t)n * K + k0 + tx] = l;
    }
}

// ================= 3-pass split-bf16 tensor-core GEMM (ldmatrix + swizzle) ==
// Tile 128x128x32; 256 thr (8 warps: 4m x 2n); 3-stage cp.async pipeline,
// one __syncthreads per iteration; MMAs interleaved (acc reuse distance 4).
__device__ __forceinline__ int sw_off(int r, int c16) {  // bf16-elem offset
    int pr = r >> 1;
    int pc = ((r & 1) << 2) | c16;
    return (pr << 6) + ((pc ^ (pr & 7)) << 3);
}
__device__ __forceinline__ void cp_async16(uint32_t dst, const void* src) {
    asm volatile("cp.async.cg.shared.global [%0], [%1], 16;\n" :: "r"(dst), "l"(src));
}
#define LDSM4(r0,r1,r2,r3,a) \
    asm volatile("ldmatrix.sync.aligned.m8n8.x4.shared.b16 {%0,%1,%2,%3}, [%4];\n" \
        : "=r"(r0), "=r"(r1), "=r"(r2), "=r"(r3) : "r"(a))
// NOTE: non-volatile — pure register op, lets nvcc/ptxas schedule freely.
#define MMA_BF16(d, a0,a1,a2,a3, b0,b1) \
    asm("mma.sync.aligned.m16n8k16.row.col.f32.bf16.bf16.f32 " \
        "{%0,%1,%2,%3},{%4,%5,%6,%7},{%8,%9},{%0,%1,%2,%3};\n" \
        : "+f"(d[0]), "+f"(d[1]), "+f"(d[2]), "+f"(d[3]) \
        : "r"(a0), "r"(a1), "r"(a2), "r"(a3), "r"(b0), "r"(b1))

#define STAGE_BYTES 32768    // 4 tiles x 8KB
#define MMA_SMEM    (3 * STAGE_BYTES)

__global__ __launch_bounds__(256)
void mma_bf16_kernel(const __nv_bfloat16* __restrict__ Ah,
                     const __nv_bfloat16* __restrict__ Al,
                     const __nv_bfloat16* __restrict__ Bh,   // [Npad][K]
                     const __nv_bfloat16* __restrict__ Bl,
                     const float* __restrict__ bias,
                     float* __restrict__ C,                  // may be null
                     __nv_bfloat16* __restrict__ Oh,         // may be null
                     __nv_bfloat16* __restrict__ Ol,
                     int M, int Nld, int Nout, int K, int act) {
    extern __shared__ __nv_bfloat16 smemb[];
    uint32_t smemBase = (uint32_t)__cvta_generic_to_shared(smemb);
    const int tid  = threadIdx.x;
    const int lane = tid & 31;
    const int wid  = tid >> 5;
    const int warp_m = wid & 3;
    const int warp_n = wid >> 2;
    const int row0 = blockIdx.y * 128;
    const int col0 = blockIdx.x * 128;

    float acc[2][8][4];
    #pragma unroll
    for (int i = 0; i < 2; i++)
        #pragma unroll
        for (int j = 0; j < 8; j++)
            #pragma unroll
            for (int k = 0; k < 4; k++) acc[i][j][k] = 0.0f;

    // cp.async per-thread chunk coords (2 chunks per tile)
    int r_[2], c_[2], soff_[2];
    #pragma unroll
    for (int j = 0; j < 2; j++) {
        int id = tid + j * 256;
        r_[j] = id >> 2;
        c_[j] = id & 3;
        soff_[j] = 2 * sw_off(r_[j], c_[j]);
    }

    // ldmatrix within-tile byte offsets
    int aoff[2], boff[4];
    #pragma unroll
    for (int mi = 0; mi < 2; mi++)
        aoff[mi] = 2 * sw_off(warp_m * 32 + mi * 16 + (lane & 15), lane >> 4);
    #pragma unroll
    for (int np = 0; np < 4; np++)
        boff[np] = 2 * sw_off(warp_n * 64 + np * 16 + ((lane & 16) >> 1) + (lane & 7),
                              (lane >> 3) & 1);

    const int nIter = K / 32;

    auto load_tiles = [&](int it) {
        uint32_t sb = smemBase + (it % 3) * STAGE_BYTES;
        int k0 = it * 32;
        #pragma unroll
        for (int j = 0; j < 2; j++) {
            size_t ga = (size_t)(row0 + r_[j]) * K + k0 + c_[j] * 8;
            size_t gb = (size_t)(col0 + r_[j]) * K + k0 + c_[j] * 8;
            cp_async16(sb + soff_[j],         Ah + ga);
            cp_async16(sb + 8192  + soff_[j], Al + ga);
            cp_async16(sb + 16384 + soff_[j], Bh + gb);
            cp_async16(sb + 24576 + soff_[j], Bl + gb);
        }
        asm volatile("cp.async.commit_group;\n");
    };

    load_tiles(0);
    load_tiles(1);

    for (int it = 0; it < nIter; it++) {
        if (it + 1 < nIter) asm volatile("cp.async.wait_group 1;\n");
        else                asm volatile("cp.async.wait_group 0;\n");
        __syncthreads();
        if (it + 2 < nIter) load_tiles(it + 2);

        uint32_t sb = smemBase + (it % 3) * STAGE_BYTES;
        #pragma unroll
        for (int kk = 0; kk < 2; kk++) {
            const int kx = kk << 5;
            uint32_t ah[2][4], al[2][4];
            #pragma unroll
            for (int mi = 0; mi < 2; mi++) {
                LDSM4(ah[mi][0], ah[mi][1], ah[mi][2], ah[mi][3],
                      sb + (aoff[mi] ^ kx));
                LDSM4(al[mi][0], al[mi][1], al[mi][2], al[mi][3],
                      sb + 8192 + (aoff[mi] ^ kx));
            }
            #pragma unroll
            for (int np = 0; np < 4; np++) {
                uint32_t bh[4], bl[4];
                LDSM4(bh[0], bh[1], bh[2], bh[3], sb + 16384 + (boff[np] ^ kx));
                LDSM4(bl[0], bl[1], bl[2], bl[3], sb + 24576 + (boff[np] ^ kx));
                float* ae0 = acc[0][np*2];     float* ao0 = acc[0][np*2+1];
                float* ae1 = acc[1][np*2];     float* ao1 = acc[1][np*2+1];
                // pass 1: ah * bl   (per-acc order preserved: bl, al, ah)
                MMA_BF16(ae0, ah[0][0], ah[0][1], ah[0][2], ah[0][3], bl[0], bl[1]);
                MMA_BF16(ao0, ah[0][0], ah[0][1], ah[0][2], ah[0][3], bl[2], bl[3]);
                MMA_BF16(ae1, ah[1][0], ah[1][1], ah[1][2], ah[1][3], bl[0], bl[1]);
                MMA_BF16(ao1, ah[1][0], ah[1][1], ah[1][2], ah[1][3], bl[2], bl[3]);
                // pass 2: al * bh
                MMA_BF16(ae0, al[0][0], al[0][1], al[0][2], al[0][3], bh[0], bh[1]);
                MMA_BF16(ao0, al[0][0], al[0][1], al[0][2], al[0][3], bh[2], bh[3]);
                MMA_BF16(ae1, al[1][0], al[1][1], al[1][2], al[1][3], bh[0], bh[1]);
                MMA_BF16(ao1, al[1][0], al[1][1], al[1][2], al[1][3], bh[2], bh[3]);
                // pass 3: ah * bh
                MMA_BF16(ae0, ah[0][0], ah[0][1], ah[0][2], ah[0][3], bh[0], bh[1]);
                MMA_BF16(ao0, ah[0][0], ah[0][1], ah[0][2], ah[0][3], bh[2], bh[3]);
                MMA_BF16(ae1, ah[1][0], ah[1][1], ah[1][2], ah[1][3], bh[0], bh[1]);
                MMA_BF16(ao1, ah[1][0], ah[1][1], ah[1][2], ah[1][3], bh[2], bh[3]);
            }
        }
    }

    // epilogue
    const int g = lane >> 2, tq = lane & 3;
    #pragma unroll
    for (int mi = 0; mi < 2; mi++) {
        int r0 = row0 + warp_m * 32 + mi * 16 + g;
        #pragma unroll
        for (int ni = 0; ni < 8; ni++) {
            int c0 = col0 + warp_n * 64 + ni * 8 + tq * 2;
            if (c0 >= Nout) continue;
            float b0 = 0.f, b1 = 0.f;
            if (bias) { b0 = bias[c0]; b1 = bias[c0 + 1]; }
            float v0 = acc[mi][ni][0] + b0;
            float v1 = acc[mi][ni][1] + b1;
            float v2 = acc[mi][ni][2] + b0;
            float v3 = acc[mi][ni][3] + b1;
            if (act == 1) {
                v0 = fmaxf(v0, 0.f); v1 = fmaxf(v1, 0.f);
                v2 = fmaxf(v2, 0.f); v3 = fmaxf(v3, 0.f);
            }
            size_t o0 = (size_t)r0 * Nld + c0;
            size_t o1 = (size_t)(r0 + 8) * Nld + c0;
            if (C) {
                *(float2*)&C[o0] = make_float2(v0, v1);
                *(float2*)&C[o1] = make_float2(v2, v3);
            }
            if (Oh) {
                __nv_bfloat162 h0 = __floats2bfloat162_rn(v0, v1);
                __nv_bfloat162 h1 = __floats2bfloat162_rn(v2, v3);
                __nv_bfloat162 l0 = __floats2bfloat162_rn(v0 - __bfloat162float(h0.x),
                                                          v1 - __bfloat162float(h0.y));
                __nv_bfloat162 l1 = __floats2bfloat162_rn(v2 - __bfloat162float(h1.x),
                                                          v3 - __bfloat162float(h1.y));
                *(__nv_bfloat162*)(Oh + o0) = h0;
                *(__nv_bfloat162*)(Oh + o1) = h1;
                *(__nv_bfloat162*)(Ol + o0) = l0;
                *(__nv_bfloat162*)(Ol + o1) = l1;
            }
        }
    }
}

// ---------------- depthwise causal conv (k=4) + SiLU, float4 vectorized -----
__global__ void conv_silu_kernel(const float* __restrict__ xz,
                                 const float* __restrict__ cw,
                                 const float* __restrict__ cb,
                                 float* __restrict__ u,
                                 __nv_bfloat16* __restrict__ uh,
                                 __nv_bfloat16* __restrict__ ul) {
    int gid = blockIdx.x * blockDim.x + threadIdx.x;   // NTOK * 64
    int tok = gid >> 6;
    int d4  = (gid & 63) * 4;
    int l   = tok & (LL - 1);
    float4 acc = *(const float4*)(cb + d4);
    float4 wv0 = *(const float4*)(cw + (d4 + 0) * 4);  // taps for channel d4
    float4 wv1 = *(const float4*)(cw + (d4 + 1) * 4);
    float4 wv2 = *(const float4*)(cw + (d4 + 2) * 4);
    float4 wv3 = *(const float4*)(cw + (d4 + 3) * 4);
    const float* wt0 = (const float*)&wv0;
    const float* wt1 = (const float*)&wv1;
    const float* wt2 = (const float*)&wv2;
    const float* wt3 = (const float*)&wv3;
    #pragma unroll
    for (int j = 0; j < 4; j++) {
        int tl = l - 3 + j;
        if (tl >= 0) {
            float4 xv = *(const float4*)(xz + (size_t)(tok - 3 + j) * (2*D_INNER) + d4);
            acc.x = fmaf(wt0[j], xv.x, acc.x);
            acc.y = fmaf(wt1[j], xv.y, acc.y);
            acc.z = fmaf(wt2[j], xv.z, acc.z);
            acc.w = fmaf(wt3[j], xv.w, acc.w);
        }
    }
    float s0 = acc.x / (1.0f + __expf(-acc.x));
    float s1 = acc.y / (1.0f + __expf(-acc.y));
    float s2 = acc.z / (1.0f + __expf(-acc.z));
    float s3 = acc.w / (1.0f + __expf(-acc.w));
    size_t base = (size_t)tok * D_INNER + d4;
    *(float4*)(u + base) = make_float4(s0, s1, s2, s3);
    __nv_bfloat162 h0 = __floats2bfloat162_rn(s0, s1);
    __nv_bfloat162 h1 = __floats2bfloat162_rn(s2, s3);
    __nv_bfloat162 l0 = __floats2bfloat162_rn(s0 - __bfloat162float(h0.x),
                                              s1 - __bfloat162float(h0.y));
    __nv_bfloat162 l1 = __floats2bfloat162_rn(s2 - __bfloat162float(h1.x),
                                              s3 - __bfloat162float(h1.y));
    *(__nv_bfloat162*)(uh + base)     = h0;
    *(__nv_bfloat162*)(uh + base + 2) = h1;
    *(__nv_bfloat162*)(ul + base)     = l0;
    *(__nv_bfloat162*)(ul + base + 2) = l1;
}

// ================= chunk-parallel selective scan =================
__global__ void scan1_kernel(const float* __restrict__ u,
                             const float* __restrict__ dbc,
                             const float* __restrict__ Wdt,
                             const float* __restrict__ bdt,
                             const float* __restrict__ A_log,
                             float* __restrict__ Sbuf,
                             float* __restrict__ Dbuf) {
    __shared__ float sR [SCH][8];
    __shared__ float sB [SCH][16];
    __shared__ float su [SCH][16];
    __shared__ float sdt[SCH][16];
    __shared__ float swt[8][16];
    __shared__ float sbd[16];
    int chunk = blockIdx.x, chg = blockIdx.y, b = blockIdx.z;
    int ch0 = chg * 16;
    int tid = threadIdx.x;
    int cl  = tid >> 4;
    int s   = tid & 15;
    int ch  = ch0 + cl;
    if (tid < 128) swt[tid >> 4][tid & 15] = Wdt[(tid >> 4) * D_INNER + ch0 + (tid & 15)];
    if (tid < 16)  sbd[tid] = bdt[ch0 + tid];
    float A = -__expf(A_log[ch * D_STATE + s]);
    float h = 0.0f, sum = 0.0f;
    size_t tokbase = (size_t)b * LL + (size_t)chunk * CLEN;
    __syncthreads();
    for (int t0 = 0; t0 < CLEN; t0 += SCH) {
        for (int i = tid; i < SCH * 8; i += 256) {
            int st = i >> 3, j = i & 7;
            sR[st][j] = dbc[(tokbase + t0 + st) * 40 + j];
        }
        for (int i = tid; i < SCH * 16; i += 256) {
            int st = i >> 4, j = i & 15;
            sB[st][j] = dbc[(tokbase + t0 + st) * 40 + 8 + j];
            su[st][j] = u  [(tokbase + t0 + st) * D_INNER + ch0 + j];
        }
        __syncthreads();
        for (int i = tid; i < SCH * 16; i += 256) {
            int st = i >> 4, j = i & 15;
            float a = sbd[j];
            #pragma unroll
            for (int jj = 0; jj < 8; jj++) a = fmaf(sR[st][jj], swt[jj][j], a);
            sdt[st][j] = (a > 20.0f) ? a : log1pf(__expf(a));
        }
        __syncthreads();
        #pragma unroll 4
        for (int i = 0; i < SCH; i++) {
            float dtv = sdt[i][cl];
            h = fmaf(__expf(dtv * A), h, dtv * su[i][cl] * sB[i][s]);
            sum += dtv;
        }
        __syncthreads();
    }
    size_t o = (((size_t)b * D_INNER + ch) * NCHUNK + chunk) * 16 + s;
    Sbuf[o] = h;
    if (s == 0) Dbuf[((size_t)b * D_INNER + ch) * NCHUNK + chunk] = sum;
}

__global__ void scanc_kernel(const float* __restrict__ A_log,
                             const float* __restrict__ Sbuf,
                             const float* __restrict__ Dbuf,
                             float* __restrict__ Hbuf) {
    int idx = blockIdx.x * 256 + threadIdx.x;
    int s  = idx & 15;
    int ch = (idx >> 4) & 255;
    int b  = idx >> 12;
    float A = -__expf(A_log[ch * D_STATE + s]);
    float h = 0.0f;
    size_t base = ((size_t)b * D_INNER + ch) * NCHUNK;
    #pragma unroll
    for (int c = 0; c < NCHUNK; c++) {
        Hbuf[(base + c) * 16 + s] = h;
        h = fmaf(__expf(A * Dbuf[base + c]), h, Sbuf[(base + c) * 16 + s]);
    }
}

__global__ void scan2_kernel(const float* __restrict__ u,
                             const float* __restrict__ dbc,
                             const float* __restrict__ xz,
                             const float* __restrict__ Wdt,
                             const float* __restrict__ bdt,
                             const float* __restrict__ A_log,
                             const float* __restrict__ Dskip,
                             const float* __restrict__ Hbuf,
                             __nv_bfloat16* __restrict__ yh,
                             __nv_bfloat16* __restrict__ yl) {
    __shared__ float sR [SCH][8];
    __shared__ float sB [SCH][16];
    __shared__ float sC [SCH][16];
    __shared__ float su [SCH][16];
    __shared__ float sz [SCH][16];
    __shared__ float sdt[SCH][16];
    __shared__ float sy [SCH][16];
    __shared__ float swt[8][16];
    __shared__ float sbd[16];
    int chunk = blockIdx.x, chg = blockIdx.y, b = blockIdx.z;
    int ch0 = chg * 16;
    int tid = threadIdx.x;
    int cl  = tid >> 4;
    int s   = tid & 15;
    int ch  = ch0 + cl;
    if (tid < 128) swt[tid >> 4][tid & 15] = Wdt[(tid >> 4) * D_INNER + ch0 + (tid & 15)];
    if (tid < 16)  sbd[tid] = bdt[ch0 + tid];
    float A  = -__expf(A_log[ch * D_STATE + s]);
    float Ds = Dskip[ch];
    float h  = Hbuf[(((size_t)b * D_INNER + ch) * NCHUNK + chunk) * 16 + s];
    size_t tokbase = (size_t)b * LL + (size_t)chunk * CLEN;
    __syncthreads();
    for (int t0 = 0; t0 < CLEN; t0 += SCH) {
        for (int i = tid; i < SCH * 8; i += 256) {
            int st = i >> 3, j = i & 7;
            sR[st][j] = dbc[(tokbase + t0 + st) * 40 + j];
        }
        for (int i = tid; i < SCH * 16; i += 256) {
            int st = i >> 4, j = i & 15;
            size_t tok = tokbase + t0 + st;
            sB[st][j] = dbc[tok * 40 + 8  + j];
            sC[st][j] = dbc[tok * 40 + 24 + j];
            su[st][j] = u  [tok * D_INNER + ch0 + j];
            sz[st][j] = xz [tok * (2*D_INNER) + D_INNER + ch0 + j];
        }
        __syncthreads();
        for (int i = tid; i < SCH * 16; i += 256) {
            int st = i >> 4, j = i & 15;
            float a = sbd[j];
            #pragma unroll
            for (int jj = 0; jj < 8; jj++) a = fmaf(sR[st][jj], swt[jj][j], a);
            sdt[st][j] = (a > 20.0f) ? a : log1pf(__expf(a));
        }
        __syncthreads();
        #pragma unroll 4
        for (int i = 0; i < SCH; i++) {
            float dtv = sdt[i][cl];
            float uv  = su [i][cl];
            h = fmaf(__expf(dtv * A), h, dtv * uv * sB[i][s]);
            float p = h * sC[i][s];
            p += __shfl_xor_sync(0xffffffffu, p, 8);
            p += __shfl_xor_sync(0xffffffffu, p, 4);
            p += __shfl_xor_sync(0xffffffffu, p, 2);
            p += __shfl_xor_sync(0xffffffffu, p, 1);
            if (s == 0) {
                float zv = sz[i][cl];
                float yv = p + uv * Ds;
                yv *= zv / (1.0f + __expf(-zv));
                sy[i][cl] = yv;
            }
        }
        __syncthreads();
        for (int i = tid; i < SCH * 16; i += 256) {
            int st = i >> 4, j = i & 15;
            float yv = sy[st][j];
            __nv_bfloat16 hh = __float2bfloat16(yv);
            __nv_bfloat16 lo = __float2bfloat16(yv - __bfloat162float(hh));
            size_t o = (tokbase + t0 + st) * D_INNER + ch0 + j;
            yh[o] = hh;
            yl[o] = lo;
        }
        __syncthreads();
    }
}

// ---------------- host launcher ----------------
extern "C" void kernel_launch(void* const* d_in, const int* in_sizes, int n_in,
                              void* d_out, int out_size) {
    const int*   tokens  = (const int*)  d_in[0];
    const float* emb     = (const float*)d_in[1];
    const float* ln_w    = (const float*)d_in[2];
    const float* ln_b    = (const float*)d_in[3];
    const float* W_in    = (const float*)d_in[4];
    const float* conv_w  = (const float*)d_in[5];
    const float* conv_b  = (const float*)d_in[6];
    const float* W_xproj = (const float*)d_in[7];
    const float* W_dt    = (const float*)d_in[8];
    const float* b_dt    = (const float*)d_in[9];
    const float* A_log   = (const float*)d_in[10];
    const float* D_skip  = (const float*)d_in[11];
    const float* W_out   = (const float*)d_in[12];
    const float* W1      = (const float*)d_in[13];
    const float* b1      = (const float*)d_in[14];
    const float* W2      = (const float*)d_in[15];
    const float* b2      = (const float*)d_in[16];
    float* out = (float*)d_out;

    float *x, *xz, *u, *dbc, *S, *Hc, *Dc;
    __nv_bfloat16 *uh, *ul, *ah, *al, *xh, *xl, *bh, *bl;
    cudaGetSymbolAddress((void**)&x,   g_x);
    cudaGetSymbolAddress((void**)&xz,  g_xz);
    cudaGetSymbolAddress((void**)&u,   g_u);
    cudaGetSymbolAddress((void**)&dbc, g_db);
    cudaGetSymbolAddress((void**)&S,   g_S);
    cudaGetSymbolAddress((void**)&Hc,  g_Hc);
    cudaGetSymbolAddress((void**)&Dc,  g_Dc);
    cudaGetSymbolAddress((void**)&uh,  g_uh);
    cudaGetSymbolAddress((void**)&ul,  g_ul);
    cudaGetSymbolAddress((void**)&ah,  g_ah);
    cudaGetSymbolAddress((void**)&al,  g_al);
    cudaGetSymbolAddress((void**)&xh,  g_xh);
    cudaGetSymbolAddress((void**)&xl,  g_xl);
    cudaGetSymbolAddress((void**)&bh,  g_bh);
    cudaGetSymbolAddress((void**)&bl,  g_bl);

    cudaFuncSetAttribute(mma_bf16_kernel,
                         cudaFuncAttributeMaxDynamicSharedMemorySize, MMA_SMEM);

    embed_kernel<<<(NTOK * 32) / 256, 256>>>(tokens, emb, x);

    for (int l = 0; l < N_LAYERS; l++) {
        const float* lw  = ln_w    + l * D_MODEL;
        const float* lb  = ln_b    + l * D_MODEL;
        const float* wi  = W_in    + (size_t)l * D_MODEL * 2 * D_INNER;
        const float* cw  = conv_w  + (size_t)l * D_INNER * D_CONV;
        const float* cb  = conv_b  + (size_t)l * D_INNER;
        const float* wx  = W_xproj + (size_t)l * D_INNER * 40;
        const float* wd  = W_dt    + (size_t)l * DT_RANK * D_INNER;
        const float* bd  = b_dt    + (size_t)l * D_INNER;
        const float* alog= A_log   + (size_t)l * D_INNER * D_STATE;
        const float* dsk = D_skip  + (size_t)l * D_INNER;
        const float* wo  = W_out   + (size_t)l * D_INNER * D_MODEL;

        ln_split_kernel<<<NTOK / 8, dim3(32, 8)>>>(x, lw, lb, ah, al);
        splitB_kernel<<<dim3(512 / 32, 128 / 32), dim3(32, 8)>>>(wi, bh, bl, 128, 512);
        // xz = ln @ W_in  [NTOK x 512], K=128
        mma_bf16_kernel<<<dim3(4, NTOK / 128), 256, MMA_SMEM>>>(
            ah, al, bh, bl, nullptr, xz, nullptr, nullptr, NTOK, 512, 512, 128, 0);
        conv_silu_kernel<<<NTOK * 64 / 256, 256>>>(xz, cw, cb, u, uh, ul);
        // dbc = u @ W_xproj  [NTOK x 40], K=256  (N padded to 128, writes guarded)
        splitB_kernel<<<dim3(128 / 32, 256 / 32), dim3(32, 8)>>>(wx, bh, bl, 256, 40);
        mma_bf16_kernel<<<dim3(1, NTOK / 128), 256, MMA_SMEM>>>(
            uh, ul, bh, bl, nullptr, dbc, nullptr, nullptr, NTOK, 40, 40, 256, 0);
        // chunk-parallel scan (dt fused)
        scan1_kernel<<<dim3(NCHUNK, 16, BB), 256>>>(u, dbc, wd, bd, alog, S, Dc);
        scanc_kernel<<<BB * 4096 / 256, 256>>>(alog, S, Dc, Hc);
        scan2_kernel<<<dim3(NCHUNK, 16, BB), 256>>>(u, dbc, xz, wd, bd, alog,
                                                    dsk, Hc, ah, al);
        // x = y @ W_out  [NTOK x 128], K=256  (+ split x for head)
        splitB_kernel<<<dim3(128 / 32, 256 / 32), dim3(32, 8)>>>(wo, bh, bl, 256, 128);
        mma_bf16_kernel<<<dim3(1, NTOK / 128), 256, MMA_SMEM>>>(
            ah, al, bh, bl, nullptr, x, xh, xl, NTOK, 128, 128, 256, 0);
    }

    // head: h1 = relu(x @ W1 + b1) -> split bf16 only
    splitB_kernel<<<dim3(512 / 32, 128 / 32), dim3(32, 8)>>>(W1, bh, bl, 128, 512);
    mma_bf16_kernel<<<dim3(4, NTOK / 128), 256, MMA_SMEM>>>(
        xh, xl, bh, bl, b1, nullptr, ah, al, NTOK, 512, 512, 128, 1);
    // out = h1 @ W2 + b2
    splitB_kernel<<<dim3(VOCAB / 32, 512 / 32), dim3(32, 8)>>>(W2, bh, bl, 512, VOCAB);
    mma_bf16_kernel<<<dim3(VOCAB / 128, NTOK / 128), 256, MMA_SMEM>>>(
        ah, al, bh, bl, b2, out, nullptr, nullptr, NTOK, VOCAB, VOCAB, 512, 0);
}